// round 6
// baseline (speedup 1.0000x reference)
#include <cuda_runtime.h>

// ---------------------------------------------------------------------------
// QuantumDMRGLayer MPS chain contraction, v3.
// Mapping: 8 lanes per chain, lane j owns output pair (2j, 2j+1) packed in one
// f32x2 register. acc = sum_i dup(v_i) * {A[i][2j], A[i][2j+1]} -> the packed
// accumulator IS the new v pair: no horizontal reduction at all.
// A0 half staged through CTA shared memory (1 LDG.64/warp/step), A1 half via
// per-warp LDG.128 double buffer. v exchanged via shared, stored duplicated
// {v,v} so it feeds fma2 multipliers directly. One __syncthreads per step.
// ---------------------------------------------------------------------------

typedef unsigned long long ull;

#define MDIM 16
#define VSTRIDE 18   // ull per sample in sh_v (16 + 2 pad -> bank-conflict-free)

// Repacked A: float4 g_A2[dir][site][c=0..15][j=0..7]
//  c in [0,8):  A0, summation-index pair i0=2c,i0+1
//  c in [8,16): A1, summation-index pair i0=2(c-8),i0+1
//  dir0 (v@M):  {A[i0][2j], A[i0][2j+1], A[i0+1][2j], A[i0+1][2j+1]}
//  dir1 (M@v):  {A[2j][n0], A[2j+1][n0], A[2j][n0+1], A[2j+1][n0+1]}
__device__ float4 g_A2[2 * 200 * 128];               // 800 KB max
__device__ float  g_vout[2][4096 * MDIM];

// ---------------------------- f32x2 helpers --------------------------------
__device__ __forceinline__ ull mul2(ull a, ull b) {
    ull d; asm("mul.rn.f32x2 %0, %1, %2;" : "=l"(d) : "l"(a), "l"(b)); return d;
}
__device__ __forceinline__ ull fma2(ull a, ull b, ull c) {
    ull d; asm("fma.rn.f32x2 %0, %1, %2, %3;" : "=l"(d) : "l"(a), "l"(b), "l"(c)); return d;
}
__device__ __forceinline__ ull add2(ull a, ull b) {
    ull d; asm("add.rn.f32x2 %0, %1, %2;" : "=l"(d) : "l"(a), "l"(b)); return d;
}
__device__ __forceinline__ ull dup2(float f) {
    ull d; asm("mov.b64 %0, {%1, %1};" : "=l"(d) : "f"(f)); return d;
}
__device__ __forceinline__ void unpack2(ull v, float& lo, float& hi) {
    asm("mov.b64 {%0, %1}, %2;" : "=f"(lo), "=f"(hi) : "l"(v));
}

// ---------------------------- prep: repack A -------------------------------
__global__ void prep_kernel(const float* __restrict__ A_mid, int nmat) {
    __shared__ float sA[512];
    int s = blockIdx.x, tid = threadIdx.x;
    reinterpret_cast<float4*>(sA)[tid] =
        reinterpret_cast<const float4*>(A_mid + (size_t)s * 512)[tid];
    __syncthreads();
    #pragma unroll
    for (int k = 0; k < 2; k++) {
        int o = tid * 2 + k;
        int dir = o >> 7, rem = o & 127, c = rem >> 3, j = rem & 7;
        const float* Bm = sA + ((c >= 8) ? 256 : 0);
        int cc = c & 7;
        float4 v;
        if (dir == 0) {
            int i0 = 2 * cc;
            v = make_float4(Bm[i0 * 16 + 2 * j],       Bm[i0 * 16 + 2 * j + 1],
                            Bm[(i0 + 1) * 16 + 2 * j], Bm[(i0 + 1) * 16 + 2 * j + 1]);
        } else {
            int n0 = 2 * cc;
            v = make_float4(Bm[2 * j * 16 + n0],     Bm[(2 * j + 1) * 16 + n0],
                            Bm[2 * j * 16 + n0 + 1], Bm[(2 * j + 1) * 16 + n0 + 1]);
        }
        g_A2[((size_t)(dir * nmat + s) * 16 + c) * 8 + j] = v;
    }
}

// ------------------------- one chain micro-step ----------------------------
__device__ __forceinline__ ull mps_step(const ull* __restrict__ sA0,   // 128 ull (shared)
                                        int j,
                                        const ulonglong2 (&A1)[8],
                                        const ull* __restrict__ vbase, // dup v (shared)
                                        float2 xx) {
    const ulonglong2* vp = reinterpret_cast<const ulonglong2*>(vbase);
    ulonglong2 v0 = vp[0], v1 = vp[1], v2 = vp[2], v3 = vp[3];
    ulonglong2 v4 = vp[4], v5 = vp[5], v6 = vp[6], v7 = vp[7];
    const ulonglong2* a0 = reinterpret_cast<const ulonglong2*>(sA0);

    ulonglong2 a;
    a = a0[0 * 8 + j];  ull e0 = mul2(v0.x, a.x), e1 = mul2(v0.y, a.y);
    a = a0[1 * 8 + j];  e0 = fma2(v1.x, a.x, e0); e1 = fma2(v1.y, a.y, e1);
    a = a0[2 * 8 + j];  e0 = fma2(v2.x, a.x, e0); e1 = fma2(v2.y, a.y, e1);
    a = a0[3 * 8 + j];  e0 = fma2(v3.x, a.x, e0); e1 = fma2(v3.y, a.y, e1);
    a = a0[4 * 8 + j];  e0 = fma2(v4.x, a.x, e0); e1 = fma2(v4.y, a.y, e1);
    a = a0[5 * 8 + j];  e0 = fma2(v5.x, a.x, e0); e1 = fma2(v5.y, a.y, e1);
    a = a0[6 * 8 + j];  e0 = fma2(v6.x, a.x, e0); e1 = fma2(v6.y, a.y, e1);
    a = a0[7 * 8 + j];  e0 = fma2(v7.x, a.x, e0); e1 = fma2(v7.y, a.y, e1);

    ull f0 = mul2(v0.x, A1[0].x), f1 = mul2(v0.y, A1[0].y);
    f0 = fma2(v1.x, A1[1].x, f0); f1 = fma2(v1.y, A1[1].y, f1);
    f0 = fma2(v2.x, A1[2].x, f0); f1 = fma2(v2.y, A1[2].y, f1);
    f0 = fma2(v3.x, A1[3].x, f0); f1 = fma2(v3.y, A1[3].y, f1);
    f0 = fma2(v4.x, A1[4].x, f0); f1 = fma2(v4.y, A1[4].y, f1);
    f0 = fma2(v5.x, A1[5].x, f0); f1 = fma2(v5.y, A1[5].y, f1);
    f0 = fma2(v6.x, A1[6].x, f0); f1 = fma2(v6.y, A1[6].y, f1);
    f0 = fma2(v7.x, A1[7].x, f0); f1 = fma2(v7.y, A1[7].y, f1);

    ull s0 = add2(e0, e1), s1 = add2(f0, f1);
    return fma2(dup2(xx.y), s1, mul2(dup2(xx.x), s0));
}

__device__ __forceinline__ void loadA1(ulonglong2 (&R)[8], const ulonglong2* p) {
    #pragma unroll
    for (int c = 0; c < 8; c++) R[c] = p[c * 8];
}

// ----------------------------- main chain kernel ---------------------------
// grid (ceil(B/16), 2), block 128: 16 chains/CTA, 8 lanes each.
__global__ void __launch_bounds__(128, 2)
chain_kernel(const float* __restrict__ inputs,
             const float* __restrict__ A_left,
             const float* __restrict__ A_right,
             const int* __restrict__ pos_ptr,
             int B, int L) {
    const int nmat = L - 2;
    const int dir  = blockIdx.y;
    const int b0   = blockIdx.x * 16;
    const int XL   = 2 * L;

    __shared__ float sh_x[16 * 400];
    __shared__ __align__(16) ull sh_v[2][16 * VSTRIDE];
    __shared__ __align__(16) ull sA0[2][128];

    const int tid = threadIdx.x;
    const int j   = tid & 7;
    const int grp = tid >> 3;           // 0..15 = sample index in CTA
    const int sOff = grp * VSTRIDE;

    // stage inputs (contiguous float4 copy)
    {
        int avail = B - b0; if (avail > 16) avail = 16;
        const float4* src = reinterpret_cast<const float4*>(inputs + (size_t)b0 * XL);
        float4* dst = reinterpret_cast<float4*>(sh_x);
        int n4 = avail * (XL / 4);
        for (int i = tid; i < n4; i += 128) dst[i] = src[i];
    }

    int pos = pos_ptr ? *pos_ptr : 98;
    if (pos < 0) pos = 0;
    if (pos > nmat) pos = nmat;
    const int nsteps = (dir == 0) ? pos : (nmat - pos);

    const ull* gbase = reinterpret_cast<const ull*>(g_A2) + (size_t)dir * nmat * 256;
    // per-matrix block = 256 ull; A0 = [0,128), A1 = [128,256)

    ulonglong2 Ar1[8], Br1[8];
    ull stg = 0;
    if (nsteps > 0) {
        int m0 = dir ? (nmat - 1) : 0;
        stg = gbase[(size_t)m0 * 256 + tid];
        sA0[0][tid] = stg;
        loadA1(Ar1, reinterpret_cast<const ulonglong2*>(gbase + (size_t)m0 * 256 + 128) + j);
    }
    __syncthreads();   // x staged + sA0[0] published

    const float* xrow = sh_x + grp * XL;

    // boundary vector init (duplicated layout)
    {
        const float* Ab = (dir == 0) ? A_left : A_right;
        const int xs = (dir == 0) ? 0 : (L - 1);
        float x0 = xrow[xs * 2], x1 = xrow[xs * 2 + 1];
        float va = fmaf(x1, Ab[MDIM + 2 * j],     x0 * Ab[2 * j]);
        float vb = fmaf(x1, Ab[MDIM + 2 * j + 1], x0 * Ab[2 * j + 1]);
        reinterpret_cast<float2*>(&sh_v[0][sOff + 2 * j])[0]     = make_float2(va, va);
        reinterpret_cast<float2*>(&sh_v[0][sOff + 2 * j + 1])[0] = make_float2(vb, vb);
    }
    __syncwarp();

    int i = 0, cur = 0, vb = 0;
    while (i < nsteps) {
        {   // body A: consume Ar1 + sA0[cur]
            if (i + 1 < nsteps) {
                int mn = dir ? (nmat - 2 - i) : (i + 1);
                stg = gbase[(size_t)mn * 256 + tid];
                loadA1(Br1, reinterpret_cast<const ulonglong2*>(gbase + (size_t)mn * 256 + 128) + j);
            }
            int site = dir ? (nmat - i) : (i + 1);
            float2 xx = *reinterpret_cast<const float2*>(xrow + site * 2);
            ull res = mps_step(sA0[cur], j, Ar1, &sh_v[vb][sOff], xx);
            float r0, r1; unpack2(res, r0, r1);
            reinterpret_cast<float2*>(&sh_v[vb ^ 1][sOff + 2 * j])[0]     = make_float2(r0, r0);
            reinterpret_cast<float2*>(&sh_v[vb ^ 1][sOff + 2 * j + 1])[0] = make_float2(r1, r1);
            if (i + 1 < nsteps) sA0[cur ^ 1][tid] = stg;
            __syncthreads();
            vb ^= 1; cur ^= 1; i++;
        }
        if (i >= nsteps) break;
        {   // body B: consume Br1 + sA0[cur]
            if (i + 1 < nsteps) {
                int mn = dir ? (nmat - 2 - i) : (i + 1);
                stg = gbase[(size_t)mn * 256 + tid];
                loadA1(Ar1, reinterpret_cast<const ulonglong2*>(gbase + (size_t)mn * 256 + 128) + j);
            }
            int site = dir ? (nmat - i) : (i + 1);
            float2 xx = *reinterpret_cast<const float2*>(xrow + site * 2);
            ull res = mps_step(sA0[cur], j, Br1, &sh_v[vb][sOff], xx);
            float r0, r1; unpack2(res, r0, r1);
            reinterpret_cast<float2*>(&sh_v[vb ^ 1][sOff + 2 * j])[0]     = make_float2(r0, r0);
            reinterpret_cast<float2*>(&sh_v[vb ^ 1][sOff + 2 * j + 1])[0] = make_float2(r1, r1);
            if (i + 1 < nsteps) sA0[cur ^ 1][tid] = stg;
            __syncthreads();
            vb ^= 1; cur ^= 1; i++;
        }
    }

    // write result pair (lo halves of the dup entries)
    {
        int b = b0 + grp;
        if (b < B) {
            float v0 = reinterpret_cast<const float*>(&sh_v[vb][sOff + 2 * j])[0];
            float v1 = reinterpret_cast<const float*>(&sh_v[vb][sOff + 2 * j + 1])[0];
            reinterpret_cast<float2*>(g_vout[dir] + (size_t)b * MDIM)[j] = make_float2(v0, v1);
        }
    }
}

// ----------------------------- final contraction ---------------------------
__global__ void finish_kernel(const float* __restrict__ T_out,
                              float* __restrict__ out, int B, int NBL) {
    __shared__ float sh_T[MDIM * MDIM * 16];
    __shared__ float sh_l[16][MDIM + 1], sh_r[16][MDIM + 1];
    int b0 = blockIdx.x * 16;
    int tid = threadIdx.x, nt = blockDim.x;
    for (int i = tid; i < MDIM * MDIM * NBL; i += nt) sh_T[i] = T_out[i];
    for (int i = tid; i < 16 * MDIM; i += nt) {
        int s = i >> 4, m = i & 15;
        int b = b0 + s;
        float lv = 0.f, rv = 0.f;
        if (b < B) { lv = g_vout[0][b * MDIM + m]; rv = g_vout[1][b * MDIM + m]; }
        sh_l[s][m] = lv; sh_r[s][m] = rv;
    }
    __syncthreads();
    if (tid < 16 * NBL) {
        int s = tid / NBL, l = tid % NBL;
        int b = b0 + s;
        float acc = 0.f;
        #pragma unroll
        for (int m = 0; m < MDIM; m++) {
            float part = 0.f;
            #pragma unroll
            for (int n = 0; n < MDIM; n++)
                part = fmaf(sh_r[s][n], sh_T[(m * MDIM + n) * NBL + l], part);
            acc = fmaf(sh_l[s][m], part, acc);
        }
        if (b < B) out[b * NBL + l] = acc;
    }
}

// ------------------------------- launch ------------------------------------
extern "C" void kernel_launch(void* const* d_in, const int* in_sizes, int n_in,
                              void* d_out, int out_size) {
    const float* inputs  = (const float*)d_in[0];
    const float* A_left  = (const float*)d_in[1];
    const float* A_mid   = (const float*)d_in[2];
    const float* A_right = (const float*)d_in[3];
    const float* T_out   = (const float*)d_in[4];
    const int*   pos_ptr = (n_in >= 6) ? (const int*)d_in[5] : nullptr;

    int M    = in_sizes[1] / 2;                 // 16
    int nmat = in_sizes[2] / (2 * M * M);       // L - 2
    int L    = nmat + 2;
    int B    = in_sizes[0] / (2 * L);
    int NBL  = in_sizes[4] / (M * M);
    (void)out_size;

    prep_kernel<<<nmat, 128>>>(A_mid, nmat);

    dim3 grid((B + 15) / 16, 2);
    chain_kernel<<<grid, 128>>>(inputs, A_left, A_right, pos_ptr, B, L);

    finish_kernel<<<(B + 15) / 16, 256>>>(T_out, (float*)d_out, B, NBL);
}

// round 8
// speedup vs baseline: 1.1186x; 1.1186x over previous
#include <cuda_runtime.h>

// ---------------------------------------------------------------------------
// QuantumDMRGLayer MPS chain contraction, v4.
// 8 lanes per chain, lane j owns output pair (2j,2j+1) packed f32x2 -> the
// packed accumulator IS the new v pair (no horizontal reduction).
// 4 chains per warp advance in the SAME instruction stream (lanes partition
// by chain). No CTA barriers in the main loop: A is register double-buffered
// per lane (16 LDG.128/warp-step, 1 line each, broadcast x4), v goes through
// warp-private shared rows with __syncwarp only.
// ---------------------------------------------------------------------------

typedef unsigned long long ull;

#define MDIM 16
#define VSTRIDE 18   // ull per sample row in sh_v (16 + 2 pad)

// Repacked A: float4 g_A2[dir][site][c=0..15][j=0..7]
//  c in [0,8):  A0 (d=0), summation pair i0=2c,i0+1
//  c in [8,16): A1 (d=1), summation pair i0=2(c-8),i0+1
//  dir0 (v@M):  {A[i0][2j], A[i0][2j+1], A[i0+1][2j], A[i0+1][2j+1]}
//  dir1 (M@v):  {A[2j][n0], A[2j+1][n0], A[2j][n0+1], A[2j+1][n0+1]}
__device__ float4 g_A2[2 * 200 * 128];               // 800 KB max
__device__ float  g_vout[2][4096 * MDIM];

// ---------------------------- f32x2 helpers --------------------------------
__device__ __forceinline__ ull mul2(ull a, ull b) {
    ull d; asm("mul.rn.f32x2 %0, %1, %2;" : "=l"(d) : "l"(a), "l"(b)); return d;
}
__device__ __forceinline__ ull fma2(ull a, ull b, ull c) {
    ull d; asm("fma.rn.f32x2 %0, %1, %2, %3;" : "=l"(d) : "l"(a), "l"(b), "l"(c)); return d;
}
__device__ __forceinline__ ull add2(ull a, ull b) {
    ull d; asm("add.rn.f32x2 %0, %1, %2;" : "=l"(d) : "l"(a), "l"(b)); return d;
}
__device__ __forceinline__ ull dup2(float f) {
    ull d; asm("mov.b64 %0, {%1, %1};" : "=l"(d) : "f"(f)); return d;
}
__device__ __forceinline__ void unpack2(ull v, float& lo, float& hi) {
    asm("mov.b64 {%0, %1}, %2;" : "=f"(lo), "=f"(hi) : "l"(v));
}

// ---------------------------- prep: repack A -------------------------------
__global__ void prep_kernel(const float* __restrict__ A_mid, int nmat) {
    __shared__ float sA[512];
    int s = blockIdx.x, tid = threadIdx.x;
    reinterpret_cast<float4*>(sA)[tid] =
        reinterpret_cast<const float4*>(A_mid + (size_t)s * 512)[tid];
    __syncthreads();
    #pragma unroll
    for (int k = 0; k < 2; k++) {
        int o = tid * 2 + k;
        int dir = o >> 7, rem = o & 127, c = rem >> 3, j = rem & 7;
        const float* Bm = sA + ((c >= 8) ? 256 : 0);
        int cc = c & 7;
        float4 v;
        if (dir == 0) {
            int i0 = 2 * cc;
            v = make_float4(Bm[i0 * 16 + 2 * j],       Bm[i0 * 16 + 2 * j + 1],
                            Bm[(i0 + 1) * 16 + 2 * j], Bm[(i0 + 1) * 16 + 2 * j + 1]);
        } else {
            int n0 = 2 * cc;
            v = make_float4(Bm[2 * j * 16 + n0],     Bm[(2 * j + 1) * 16 + n0],
                            Bm[2 * j * 16 + n0 + 1], Bm[(2 * j + 1) * 16 + n0 + 1]);
        }
        g_A2[((size_t)(dir * nmat + s) * 16 + c) * 8 + j] = v;
    }
}

// ------------------------- one chain micro-step ----------------------------
// A[0..7] = A0 chunks, A[8..15] = A1 chunks (this lane's j column-pairs).
__device__ __forceinline__ ull mps_step(const ulonglong2 (&A)[16],
                                        const ull* __restrict__ vbase, // dup v (shared)
                                        float2 xx) {
    const ulonglong2* vp = reinterpret_cast<const ulonglong2*>(vbase);
    ulonglong2 v0 = vp[0], v1 = vp[1], v2 = vp[2], v3 = vp[3];
    ulonglong2 v4 = vp[4], v5 = vp[5], v6 = vp[6], v7 = vp[7];

    ull e0 = mul2(v0.x, A[0].x), e1 = mul2(v0.y, A[0].y);
    ull f0 = mul2(v0.x, A[8].x), f1 = mul2(v0.y, A[8].y);
    e0 = fma2(v1.x, A[1].x, e0);  e1 = fma2(v1.y, A[1].y, e1);
    f0 = fma2(v1.x, A[9].x, f0);  f1 = fma2(v1.y, A[9].y, f1);
    e0 = fma2(v2.x, A[2].x, e0);  e1 = fma2(v2.y, A[2].y, e1);
    f0 = fma2(v2.x, A[10].x, f0); f1 = fma2(v2.y, A[10].y, f1);
    e0 = fma2(v3.x, A[3].x, e0);  e1 = fma2(v3.y, A[3].y, e1);
    f0 = fma2(v3.x, A[11].x, f0); f1 = fma2(v3.y, A[11].y, f1);
    e0 = fma2(v4.x, A[4].x, e0);  e1 = fma2(v4.y, A[4].y, e1);
    f0 = fma2(v4.x, A[12].x, f0); f1 = fma2(v4.y, A[12].y, f1);
    e0 = fma2(v5.x, A[5].x, e0);  e1 = fma2(v5.y, A[5].y, e1);
    f0 = fma2(v5.x, A[13].x, f0); f1 = fma2(v5.y, A[13].y, f1);
    e0 = fma2(v6.x, A[6].x, e0);  e1 = fma2(v6.y, A[6].y, e1);
    f0 = fma2(v6.x, A[14].x, f0); f1 = fma2(v6.y, A[14].y, f1);
    e0 = fma2(v7.x, A[7].x, e0);  e1 = fma2(v7.y, A[7].y, e1);
    f0 = fma2(v7.x, A[15].x, f0); f1 = fma2(v7.y, A[15].y, f1);

    ull s0 = add2(e0, e1), s1 = add2(f0, f1);
    return fma2(dup2(xx.y), s1, mul2(dup2(xx.x), s0));
}

__device__ __forceinline__ void loadA(ulonglong2 (&R)[16], const ulonglong2* p) {
    #pragma unroll
    for (int c = 0; c < 16; c++) R[c] = p[c * 8];   // stride 128B, 1 line each
}

// ----------------------------- main chain kernel ---------------------------
// grid (ceil(B/16), 2), block 128: 16 chains/CTA, 8 lanes each, 4 chains/warp.
__global__ void __launch_bounds__(128, 2)
chain_kernel(const float* __restrict__ inputs,
             const float* __restrict__ A_left,
             const float* __restrict__ A_right,
             const int* __restrict__ pos_ptr,
             int B, int L) {
    const int nmat = L - 2;
    const int dir  = blockIdx.y;
    const int b0   = blockIdx.x * 16;
    const int XL   = 2 * L;

    __shared__ float sh_x[16 * 400];
    __shared__ __align__(16) ull sh_v[2][16 * VSTRIDE];

    const int tid = threadIdx.x;
    const int j   = tid & 7;
    const int grp = tid >> 3;           // 0..15 = sample index in CTA
    const int sOff = grp * VSTRIDE;

    // stage inputs (contiguous float4 copy), one-time CTA barrier
    {
        int avail = B - b0; if (avail > 16) avail = 16;
        const float4* src = reinterpret_cast<const float4*>(inputs + (size_t)b0 * XL);
        float4* dst = reinterpret_cast<float4*>(sh_x);
        int n4 = avail * (XL / 4);
        for (int i = tid; i < n4; i += 128) dst[i] = src[i];
    }

    int pos = pos_ptr ? *pos_ptr : 98;
    if (pos < 0) pos = 0;
    if (pos > nmat) pos = nmat;
    const int nsteps = (dir == 0) ? pos : (nmat - pos);

    const float* xrow = sh_x + grp * XL;

    // A walk: per (dir,site) block of 128 ulonglong2; lane j chunk c at c*8+j.
    const ulonglong2* Abase =
        reinterpret_cast<const ulonglong2*>(g_A2) + (size_t)dir * nmat * 128 + j;
    const ptrdiff_t mstep = dir ? -128 : 128;
    const int m0 = dir ? (nmat - 1) : 0;
    const ulonglong2* pA = Abase + (ptrdiff_t)m0 * 128;

    ulonglong2 Ar[16], Br[16];
    if (nsteps > 0) loadA(Ar, pA);
    const ulonglong2* pAn = pA + mstep;

    __syncthreads();   // x staged

    // boundary vector init (duplicated layout)
    {
        const float* Ab = (dir == 0) ? A_left : A_right;
        const int xs = (dir == 0) ? 0 : (L - 1);
        float x0 = xrow[xs * 2], x1 = xrow[xs * 2 + 1];
        float va = fmaf(x1, Ab[MDIM + 2 * j],     x0 * Ab[2 * j]);
        float vb_ = fmaf(x1, Ab[MDIM + 2 * j + 1], x0 * Ab[2 * j + 1]);
        reinterpret_cast<float2*>(&sh_v[0][sOff + 2 * j])[0]     = make_float2(va, va);
        reinterpret_cast<float2*>(&sh_v[0][sOff + 2 * j + 1])[0] = make_float2(vb_, vb_);
    }
    __syncwarp();

    // x walk: dir0 sites 1..pos ascending, dir1 sites nmat..pos+1 descending
    const float* xs = xrow + (dir ? nmat * 2 : 2);
    const ptrdiff_t xstep = dir ? -2 : 2;

    int i = 0, vb = 0;
    while (i < nsteps) {
        {   // body A: consume Ar, prefetch into Br
            if (i + 1 < nsteps) { loadA(Br, pAn); pAn += mstep; }
            float2 xx = *reinterpret_cast<const float2*>(xs); xs += xstep;
            ull res = mps_step(Ar, &sh_v[vb][sOff], xx);
            float r0, r1; unpack2(res, r0, r1);
            reinterpret_cast<float2*>(&sh_v[vb ^ 1][sOff + 2 * j])[0]     = make_float2(r0, r0);
            reinterpret_cast<float2*>(&sh_v[vb ^ 1][sOff + 2 * j + 1])[0] = make_float2(r1, r1);
            __syncwarp();
            vb ^= 1; i++;
        }
        if (i >= nsteps) break;
        {   // body B: consume Br, prefetch into Ar
            if (i + 1 < nsteps) { loadA(Ar, pAn); pAn += mstep; }
            float2 xx = *reinterpret_cast<const float2*>(xs); xs += xstep;
            ull res = mps_step(Br, &sh_v[vb][sOff], xx);
            float r0, r1; unpack2(res, r0, r1);
            reinterpret_cast<float2*>(&sh_v[vb ^ 1][sOff + 2 * j])[0]     = make_float2(r0, r0);
            reinterpret_cast<float2*>(&sh_v[vb ^ 1][sOff + 2 * j + 1])[0] = make_float2(r1, r1);
            __syncwarp();
            vb ^= 1; i++;
        }
    }

    // write result pair (lo halves of the dup entries)
    {
        int b = b0 + grp;
        if (b < B) {
            float v0 = reinterpret_cast<const float*>(&sh_v[vb][sOff + 2 * j])[0];
            float v1 = reinterpret_cast<const float*>(&sh_v[vb][sOff + 2 * j + 1])[0];
            reinterpret_cast<float2*>(g_vout[dir] + (size_t)b * MDIM)[j] = make_float2(v0, v1);
        }
    }
}

// ----------------------------- final contraction ---------------------------
__global__ void finish_kernel(const float* __restrict__ T_out,
                              float* __restrict__ out, int B, int NBL) {
    __shared__ float sh_T[MDIM * MDIM * 16];
    __shared__ float sh_l[16][MDIM + 1], sh_r[16][MDIM + 1];
    int b0 = blockIdx.x * 16;
    int tid = threadIdx.x, nt = blockDim.x;
    for (int i = tid; i < MDIM * MDIM * NBL; i += nt) sh_T[i] = T_out[i];
    for (int i = tid; i < 16 * MDIM; i += nt) {
        int s = i >> 4, m = i & 15;
        int b = b0 + s;
        float lv = 0.f, rv = 0.f;
        if (b < B) { lv = g_vout[0][b * MDIM + m]; rv = g_vout[1][b * MDIM + m]; }
        sh_l[s][m] = lv; sh_r[s][m] = rv;
    }
    __syncthreads();
    if (tid < 16 * NBL) {
        int s = tid / NBL, l = tid % NBL;
        int b = b0 + s;
        float acc = 0.f;
        #pragma unroll
        for (int m = 0; m < MDIM; m++) {
            float part = 0.f;
            #pragma unroll
            for (int n = 0; n < MDIM; n++)
                part = fmaf(sh_r[s][n], sh_T[(m * MDIM + n) * NBL + l], part);
            acc = fmaf(sh_l[s][m], part, acc);
        }
        if (b < B) out[b * NBL + l] = acc;
    }
}

// ------------------------------- launch ------------------------------------
extern "C" void kernel_launch(void* const* d_in, const int* in_sizes, int n_in,
                              void* d_out, int out_size) {
    const float* inputs  = (const float*)d_in[0];
    const float* A_left  = (const float*)d_in[1];
    const float* A_mid   = (const float*)d_in[2];
    const float* A_right = (const float*)d_in[3];
    const float* T_out   = (const float*)d_in[4];
    const int*   pos_ptr = (n_in >= 6) ? (const int*)d_in[5] : nullptr;

    int M    = in_sizes[1] / 2;                 // 16
    int nmat = in_sizes[2] / (2 * M * M);       // L - 2
    int L    = nmat + 2;
    int B    = in_sizes[0] / (2 * L);
    int NBL  = in_sizes[4] / (M * M);
    (void)out_size;

    prep_kernel<<<nmat, 128>>>(A_mid, nmat);

    dim3 grid((B + 15) / 16, 2);
    chain_kernel<<<grid, 128>>>(inputs, A_left, A_right, pos_ptr, B, L);

    finish_kernel<<<(B + 15) / 16, 256>>>(T_out, (float*)d_out, B, NBL);
}

// round 9
// speedup vs baseline: 1.1585x; 1.0357x over previous
#include <cuda_runtime.h>

// ---------------------------------------------------------------------------
// QuantumDMRGLayer MPS chain contraction, v5.
// 8 lanes per group, lane j owns output pair (2j,2j+1) packed f32x2 (no
// horizontal reduction). Each group advances TWO samples per step with the
// SAME A registers (8 samples/warp) -> A wavefronts per sample halved vs v4.
// No CTA barriers in the loop; v via warp-private shared + __syncwarp; A is
// register double-buffered (16 LDG.128/warp-step, 1 line each).
// ---------------------------------------------------------------------------

typedef unsigned long long ull;

#define MDIM 16
#define VSTRIDE 18   // ull per sample row in sh_v (16 + 2 pad)

// Repacked A: float4 g_A2[dir][site][c=0..15][j=0..7]
//  c in [0,8):  A0, summation pair i0=2c,i0+1 ; c in [8,16): A1
//  dir0 (v@M):  {A[i0][2j], A[i0][2j+1], A[i0+1][2j], A[i0+1][2j+1]}
//  dir1 (M@v):  {A[2j][n0], A[2j+1][n0], A[2j][n0+1], A[2j+1][n0+1]}
__device__ float4 g_A2[2 * 200 * 128];               // 800 KB max
__device__ float  g_vout[2][4096 * MDIM];

// ---------------------------- f32x2 helpers --------------------------------
__device__ __forceinline__ ull mul2(ull a, ull b) {
    ull d; asm("mul.rn.f32x2 %0, %1, %2;" : "=l"(d) : "l"(a), "l"(b)); return d;
}
__device__ __forceinline__ ull fma2(ull a, ull b, ull c) {
    ull d; asm("fma.rn.f32x2 %0, %1, %2, %3;" : "=l"(d) : "l"(a), "l"(b), "l"(c)); return d;
}
__device__ __forceinline__ ull add2(ull a, ull b) {
    ull d; asm("add.rn.f32x2 %0, %1, %2;" : "=l"(d) : "l"(a), "l"(b)); return d;
}
__device__ __forceinline__ ull dup2(float f) {
    ull d; asm("mov.b64 %0, {%1, %1};" : "=l"(d) : "f"(f)); return d;
}
__device__ __forceinline__ void unpack2(ull v, float& lo, float& hi) {
    asm("mov.b64 {%0, %1}, %2;" : "=f"(lo), "=f"(hi) : "l"(v));
}

// ---------------------------- prep: repack A -------------------------------
// 256 threads, 2 sites per block.
__global__ void prep_kernel(const float* __restrict__ A_mid, int nmat) {
    __shared__ float sA[1024];
    int s0 = blockIdx.x * 2, tid = threadIdx.x;
    int nsite = (s0 + 1 < nmat) ? 2 : 1;
    if (tid < nsite * 128)
        reinterpret_cast<float4*>(sA)[tid] =
            reinterpret_cast<const float4*>(A_mid + (size_t)s0 * 512)[tid];
    __syncthreads();
    #pragma unroll
    for (int k = 0; k < 2; k++) {
        int o = tid * 2 + k;                 // [0, 512)
        int sl  = o >> 8;                    // local site 0/1
        if (sl >= nsite) continue;
        int rem = o & 255;
        int dir = rem >> 7, c = (rem >> 3) & 15, j = rem & 7;
        const float* Bm = sA + sl * 512 + ((c >= 8) ? 256 : 0);
        int cc = c & 7;
        float4 v;
        if (dir == 0) {
            int i0 = 2 * cc;
            v = make_float4(Bm[i0 * 16 + 2 * j],       Bm[i0 * 16 + 2 * j + 1],
                            Bm[(i0 + 1) * 16 + 2 * j], Bm[(i0 + 1) * 16 + 2 * j + 1]);
        } else {
            int n0 = 2 * cc;
            v = make_float4(Bm[2 * j * 16 + n0],     Bm[(2 * j + 1) * 16 + n0],
                            Bm[2 * j * 16 + n0 + 1], Bm[(2 * j + 1) * 16 + n0 + 1]);
        }
        int s = s0 + sl;
        g_A2[((size_t)(dir * nmat + s) * 16 + c) * 8 + j] = v;
    }
}

// ------------------------- one chain micro-step ----------------------------
__device__ __forceinline__ ull mps_step(const ulonglong2 (&A)[16],
                                        const ull* __restrict__ vbase,
                                        float2 xx) {
    const ulonglong2* vp = reinterpret_cast<const ulonglong2*>(vbase);
    ulonglong2 v0 = vp[0], v1 = vp[1], v2 = vp[2], v3 = vp[3];
    ulonglong2 v4 = vp[4], v5 = vp[5], v6 = vp[6], v7 = vp[7];

    ull e0 = mul2(v0.x, A[0].x), e1 = mul2(v0.y, A[0].y);
    ull f0 = mul2(v0.x, A[8].x), f1 = mul2(v0.y, A[8].y);
    e0 = fma2(v1.x, A[1].x, e0);  e1 = fma2(v1.y, A[1].y, e1);
    f0 = fma2(v1.x, A[9].x, f0);  f1 = fma2(v1.y, A[9].y, f1);
    e0 = fma2(v2.x, A[2].x, e0);  e1 = fma2(v2.y, A[2].y, e1);
    f0 = fma2(v2.x, A[10].x, f0); f1 = fma2(v2.y, A[10].y, f1);
    e0 = fma2(v3.x, A[3].x, e0);  e1 = fma2(v3.y, A[3].y, e1);
    f0 = fma2(v3.x, A[11].x, f0); f1 = fma2(v3.y, A[11].y, f1);
    e0 = fma2(v4.x, A[4].x, e0);  e1 = fma2(v4.y, A[4].y, e1);
    f0 = fma2(v4.x, A[12].x, f0); f1 = fma2(v4.y, A[12].y, f1);
    e0 = fma2(v5.x, A[5].x, e0);  e1 = fma2(v5.y, A[5].y, e1);
    f0 = fma2(v5.x, A[13].x, f0); f1 = fma2(v5.y, A[13].y, f1);
    e0 = fma2(v6.x, A[6].x, e0);  e1 = fma2(v6.y, A[6].y, e1);
    f0 = fma2(v6.x, A[14].x, f0); f1 = fma2(v6.y, A[14].y, f1);
    e0 = fma2(v7.x, A[7].x, e0);  e1 = fma2(v7.y, A[7].y, e1);
    f0 = fma2(v7.x, A[15].x, f0); f1 = fma2(v7.y, A[15].y, f1);

    ull s0 = add2(e0, e1), s1 = add2(f0, f1);
    return fma2(dup2(xx.y), s1, mul2(dup2(xx.x), s0));
}

__device__ __forceinline__ void loadA(ulonglong2 (&R)[16], const ulonglong2* p) {
    #pragma unroll
    for (int c = 0; c < 16; c++) R[c] = p[c * 8];   // 128B stride, 1 line each
}

// ----------------------------- main chain kernel ---------------------------
// grid (ceil(B/16), 2), block 64: 16 chains/CTA, 8 lanes/group, 2 samples per
// group advanced sequentially with the same A registers.
__global__ void __launch_bounds__(64)
chain_kernel(const float* __restrict__ inputs,
             const float* __restrict__ A_left,
             const float* __restrict__ A_right,
             const int* __restrict__ pos_ptr,
             int B, int L) {
    const int nmat = L - 2;
    const int dir  = blockIdx.y;
    const int b0   = blockIdx.x * 16;
    const int XL   = 2 * L;

    __shared__ float sh_x[16 * 400];
    __shared__ __align__(16) ull sh_v[2][16 * VSTRIDE];

    const int tid = threadIdx.x;
    const int j   = tid & 7;
    const int grp = tid >> 3;           // 0..7
    const int sa  = grp * 2;            // first sample of this group
    const int offA = sa * VSTRIDE;
    const int offB = (sa + 1) * VSTRIDE;

    // stage inputs
    {
        int avail = B - b0; if (avail > 16) avail = 16;
        const float4* src = reinterpret_cast<const float4*>(inputs + (size_t)b0 * XL);
        float4* dst = reinterpret_cast<float4*>(sh_x);
        int n4 = avail * (XL / 4);
        for (int i = tid; i < n4; i += 64) dst[i] = src[i];
    }

    int pos = pos_ptr ? *pos_ptr : 98;
    if (pos < 0) pos = 0;
    if (pos > nmat) pos = nmat;
    const int nsteps = (dir == 0) ? pos : (nmat - pos);

    // A walk
    const ulonglong2* Abase =
        reinterpret_cast<const ulonglong2*>(g_A2) + (size_t)dir * nmat * 128 + j;
    const ptrdiff_t mstep = dir ? -128 : 128;
    const int m0 = dir ? (nmat - 1) : 0;
    const ulonglong2* pA = Abase + (ptrdiff_t)m0 * 128;

    ulonglong2 Ar[16], Br[16];
    if (nsteps > 0) loadA(Ar, pA);
    const ulonglong2* pAn = pA + mstep;

    __syncthreads();   // x staged

    const float* xrowA = sh_x + (size_t)sa * XL;
    const float* xrowB = xrowA + XL;

    // boundary vector init (duplicated layout), both samples
    {
        const float* Ab = (dir == 0) ? A_left : A_right;
        const int xsit = (dir == 0) ? 0 : (L - 1);
        float e0 = Ab[2 * j], e1 = Ab[MDIM + 2 * j];
        float g0 = Ab[2 * j + 1], g1 = Ab[MDIM + 2 * j + 1];
        float xa0 = xrowA[xsit * 2], xa1 = xrowA[xsit * 2 + 1];
        float xb0 = xrowB[xsit * 2], xb1 = xrowB[xsit * 2 + 1];
        float va = fmaf(xa1, e1, xa0 * e0), vaa = fmaf(xa1, g1, xa0 * g0);
        float vb = fmaf(xb1, e1, xb0 * e0), vbb = fmaf(xb1, g1, xb0 * g0);
        reinterpret_cast<float4*>(&sh_v[0][offA + 2 * j])[0] = make_float4(va, va, vaa, vaa);
        reinterpret_cast<float4*>(&sh_v[0][offB + 2 * j])[0] = make_float4(vb, vb, vbb, vbb);
    }
    __syncwarp();

    // x walk
    const float* xsA = xrowA + (dir ? nmat * 2 : 2);
    const float* xsB = xrowB + (dir ? nmat * 2 : 2);
    const ptrdiff_t xstep = dir ? -2 : 2;

    int i = 0, vb = 0;
    while (i < nsteps) {
        {   // consume Ar, prefetch Br
            if (i + 1 < nsteps) { loadA(Br, pAn); pAn += mstep; }
            float2 xxA = *reinterpret_cast<const float2*>(xsA); xsA += xstep;
            float2 xxB = *reinterpret_cast<const float2*>(xsB); xsB += xstep;
            ull rA = mps_step(Ar, &sh_v[vb][offA], xxA);
            ull rB = mps_step(Ar, &sh_v[vb][offB], xxB);
            float a0, a1, c0, c1; unpack2(rA, a0, a1); unpack2(rB, c0, c1);
            reinterpret_cast<float4*>(&sh_v[vb ^ 1][offA + 2 * j])[0] = make_float4(a0, a0, a1, a1);
            reinterpret_cast<float4*>(&sh_v[vb ^ 1][offB + 2 * j])[0] = make_float4(c0, c0, c1, c1);
            __syncwarp();
            vb ^= 1; i++;
        }
        if (i >= nsteps) break;
        {   // consume Br, prefetch Ar
            if (i + 1 < nsteps) { loadA(Ar, pAn); pAn += mstep; }
            float2 xxA = *reinterpret_cast<const float2*>(xsA); xsA += xstep;
            float2 xxB = *reinterpret_cast<const float2*>(xsB); xsB += xstep;
            ull rA = mps_step(Br, &sh_v[vb][offA], xxA);
            ull rB = mps_step(Br, &sh_v[vb][offB], xxB);
            float a0, a1, c0, c1; unpack2(rA, a0, a1); unpack2(rB, c0, c1);
            reinterpret_cast<float4*>(&sh_v[vb ^ 1][offA + 2 * j])[0] = make_float4(a0, a0, a1, a1);
            reinterpret_cast<float4*>(&sh_v[vb ^ 1][offB + 2 * j])[0] = make_float4(c0, c0, c1, c1);
            __syncwarp();
            vb ^= 1; i++;
        }
    }

    // write result pairs (lo halves of the dup entries)
    {
        int bA = b0 + sa, bB = bA + 1;
        if (bA < B) {
            float v0 = reinterpret_cast<const float*>(&sh_v[vb][offA + 2 * j])[0];
            float v1 = reinterpret_cast<const float*>(&sh_v[vb][offA + 2 * j + 1])[0];
            reinterpret_cast<float2*>(g_vout[dir] + (size_t)bA * MDIM)[j] = make_float2(v0, v1);
        }
        if (bB < B) {
            float v0 = reinterpret_cast<const float*>(&sh_v[vb][offB + 2 * j])[0];
            float v1 = reinterpret_cast<const float*>(&sh_v[vb][offB + 2 * j + 1])[0];
            reinterpret_cast<float2*>(g_vout[dir] + (size_t)bB * MDIM)[j] = make_float2(v0, v1);
        }
    }
}

// ----------------------------- final contraction ---------------------------
__global__ void finish_kernel(const float* __restrict__ T_out,
                              float* __restrict__ out, int B, int NBL) {
    __shared__ float sh_T[MDIM * MDIM * 16];
    __shared__ float sh_l[16][MDIM + 1], sh_r[16][MDIM + 1];
    int b0 = blockIdx.x * 16;
    int tid = threadIdx.x, nt = blockDim.x;
    for (int i = tid; i < MDIM * MDIM * NBL; i += nt) sh_T[i] = T_out[i];
    for (int i = tid; i < 16 * MDIM; i += nt) {
        int s = i >> 4, m = i & 15;
        int b = b0 + s;
        float lv = 0.f, rv = 0.f;
        if (b < B) { lv = g_vout[0][b * MDIM + m]; rv = g_vout[1][b * MDIM + m]; }
        sh_l[s][m] = lv; sh_r[s][m] = rv;
    }
    __syncthreads();
    if (tid < 16 * NBL) {
        int s = tid / NBL, l = tid % NBL;
        int b = b0 + s;
        float acc = 0.f;
        #pragma unroll
        for (int m = 0; m < MDIM; m++) {
            float part = 0.f;
            #pragma unroll
            for (int n = 0; n < MDIM; n++)
                part = fmaf(sh_r[s][n], sh_T[(m * MDIM + n) * NBL + l], part);
            acc = fmaf(sh_l[s][m], part, acc);
        }
        if (b < B) out[b * NBL + l] = acc;
    }
}

// ------------------------------- launch ------------------------------------
extern "C" void kernel_launch(void* const* d_in, const int* in_sizes, int n_in,
                              void* d_out, int out_size) {
    const float* inputs  = (const float*)d_in[0];
    const float* A_left  = (const float*)d_in[1];
    const float* A_mid   = (const float*)d_in[2];
    const float* A_right = (const float*)d_in[3];
    const float* T_out   = (const float*)d_in[4];
    const int*   pos_ptr = (n_in >= 6) ? (const int*)d_in[5] : nullptr;

    int M    = in_sizes[1] / 2;                 // 16
    int nmat = in_sizes[2] / (2 * M * M);       // L - 2
    int L    = nmat + 2;
    int B    = in_sizes[0] / (2 * L);
    int NBL  = in_sizes[4] / (M * M);
    (void)out_size;

    prep_kernel<<<(nmat + 1) / 2, 256>>>(A_mid, nmat);

    dim3 grid((B + 15) / 16, 2);
    chain_kernel<<<grid, 64>>>(inputs, A_left, A_right, pos_ptr, B, L);

    finish_kernel<<<(B + 15) / 16, 256>>>(T_out, (float*)d_out, B, NBL);
}